// round 16
// baseline (speedup 1.0000x reference)
#include <cuda_runtime.h>
#include <cuda_fp16.h>
#include <math.h>
#include <stdint.h>

#define Bsz   4
#define Sq    2048
#define Dm    2048
#define Hh    16
#define HDim  128
#define Mrows (Bsz*Sq)      /* 8192 */
#define QKVN  (3*Dm)        /* 6144 */

// ---------------- scratch (device globals; no allocation allowed) ----------
__device__ __half g_xh[(size_t)Mrows * Dm];     // LN out hi/lo (fp16 split)
__device__ __half g_xl[(size_t)Mrows * Dm];
__device__ __half g_qh[(size_t)Mrows * QKVN];   // qkv projection hi/lo
__device__ __half g_ql[(size_t)Mrows * QKVN];   // (lo only consumed for Q cols)
__device__ __half g_ah[(size_t)Mrows * Dm];     // attn out hi/lo
__device__ __half g_al[(size_t)Mrows * Dm];
__device__ __half g_wqh[(size_t)QKVN * Dm];     // W_qkv^T hi
__device__ __half g_wph[(size_t)Dm * Dm];       // W_proj^T hi

// ---------------- small helpers --------------------------------------------
__device__ __forceinline__ void hsplit(float x, __half& h, __half& l) {
    h = __float2half_rn(x);
    l = __float2half_rn(x - __half2float(h));
}
__device__ __forceinline__ uint32_t packh2(__half a, __half b) {
    __half2 h = __halves2half2(a, b);
    return *(uint32_t*)&h;
}

// ---------------- Ampere-era primitives (valid on plain sm_103 target) -----
__device__ __forceinline__ uint32_t cvta_smem(const void* p) {
    return (uint32_t)__cvta_generic_to_shared(p);
}
__device__ __forceinline__ void cp16(uint32_t s, const void* g) {
    asm volatile("cp.async.cg.shared.global [%0], [%1], 16;" :: "r"(s), "l"(g));
}
__device__ __forceinline__ void cp_commit() {
    asm volatile("cp.async.commit_group;" ::: "memory");
}
template<int W> __device__ __forceinline__ void cp_wait() {
    asm volatile("cp.async.wait_group %0;" :: "n"(W) : "memory");
}
__device__ __forceinline__ void ldsm4(uint32_t* r, uint32_t addr) {
    asm volatile("ldmatrix.sync.aligned.m8n8.x4.shared.b16 {%0,%1,%2,%3}, [%4];"
                 : "=r"(r[0]), "=r"(r[1]), "=r"(r[2]), "=r"(r[3]) : "r"(addr));
}
__device__ __forceinline__ void ldsm4t(uint32_t* r, uint32_t addr) {
    asm volatile("ldmatrix.sync.aligned.m8n8.x4.trans.shared.b16 {%0,%1,%2,%3}, [%4];"
                 : "=r"(r[0]), "=r"(r[1]), "=r"(r[2]), "=r"(r[3]) : "r"(addr));
}
__device__ __forceinline__ void mma16816(float* c, const uint32_t* a, const uint32_t* b) {
    asm volatile("mma.sync.aligned.m16n8k16.row.col.f32.f16.f16.f32 "
                 "{%0,%1,%2,%3}, {%4,%5,%6,%7}, {%8,%9}, {%0,%1,%2,%3};"
                 : "+f"(c[0]), "+f"(c[1]), "+f"(c[2]), "+f"(c[3])
                 : "r"(a[0]), "r"(a[1]), "r"(a[2]), "r"(a[3]),
                   "r"(b[0]), "r"(b[1]));
}

// ---------------- LayerNorm: one block per row, writes fp16 hi/lo ----------
__global__ void __launch_bounds__(256) ln_kernel(
    const float* __restrict__ x, const float* __restrict__ gamma,
    const float* __restrict__ beta)
{
    const int row = blockIdx.x, t = threadIdx.x;
    const float4* xr = (const float4*)(x + (size_t)row * Dm);
    float4 v0 = xr[t], v1 = xr[t + 256];
    float s  = v0.x + v0.y + v0.z + v0.w + v1.x + v1.y + v1.z + v1.w;
    float ss = v0.x*v0.x + v0.y*v0.y + v0.z*v0.z + v0.w*v0.w
             + v1.x*v1.x + v1.y*v1.y + v1.z*v1.z + v1.w*v1.w;
    #pragma unroll
    for (int o = 16; o; o >>= 1) {
        s  += __shfl_xor_sync(0xffffffffu, s,  o);
        ss += __shfl_xor_sync(0xffffffffu, ss, o);
    }
    __shared__ float sh[16];
    const int w = t >> 5;
    if ((t & 31) == 0) { sh[w] = s; sh[8 + w] = ss; }
    __syncthreads();
    s = 0.f; ss = 0.f;
    #pragma unroll
    for (int i = 0; i < 8; i++) { s += sh[i]; ss += sh[8 + i]; }
    const float mean = s * (1.0f / Dm);
    const float var  = ss * (1.0f / Dm) - mean * mean;
    const float rstd = rsqrtf(var + 1e-5f);

    const float4* g4 = (const float4*)gamma;
    const float4* b4 = (const float4*)beta;
    float4 G0 = g4[t], G1 = g4[t + 256], B0 = b4[t], B1 = b4[t + 256];
    float4 o0, o1;
    o0.x = (v0.x - mean) * rstd * G0.x + B0.x;
    o0.y = (v0.y - mean) * rstd * G0.y + B0.y;
    o0.z = (v0.z - mean) * rstd * G0.z + B0.z;
    o0.w = (v0.w - mean) * rstd * G0.w + B0.w;
    o1.x = (v1.x - mean) * rstd * G1.x + B1.x;
    o1.y = (v1.y - mean) * rstd * G1.y + B1.y;
    o1.z = (v1.z - mean) * rstd * G1.z + B1.z;
    o1.w = (v1.w - mean) * rstd * G1.w + B1.w;

    auto store4 = [&](float4 v, int c0) {
        __half h0,l0,h1,l1,h2,l2,h3,l3;
        hsplit(v.x,h0,l0); hsplit(v.y,h1,l1); hsplit(v.z,h2,l2); hsplit(v.w,h3,l3);
        size_t base = (size_t)row * Dm + c0;
        *(__half2*)&g_xh[base]     = __halves2half2(h0, h1);
        *(__half2*)&g_xh[base + 2] = __halves2half2(h2, h3);
        *(__half2*)&g_xl[base]     = __halves2half2(l0, l1);
        *(__half2*)&g_xl[base + 2] = __halves2half2(l2, l3);
    };
    store4(o0, t * 4);
    store4(o1, 1024 + t * 4);
}

// ---------------- W transpose + fp16 convert (hi only) ---------------------
__global__ void wconv_kernel(const float* __restrict__ W,
                             __half* __restrict__ Th, int K, int N)
{
    __shared__ float tile[32][33];
    const int tx = threadIdx.x, ty = threadIdx.y;
    const int n0 = blockIdx.x * 32, k0 = blockIdx.y * 32;
    #pragma unroll
    for (int r = 0; r < 32; r += 8)
        tile[ty + r][tx] = W[(size_t)(k0 + ty + r) * N + n0 + tx];
    __syncthreads();
    #pragma unroll
    for (int r = 0; r < 32; r += 8) {
        Th[(size_t)(n0 + ty + r) * K + k0 + tx] = __float2half_rn(tile[tx][ty + r]);
    }
}

// ---------------- HMMA GEMM: C = (Ah+Al)[MxK] * Bh^T[KxN] + bias -----------
// 2-term fp16 split, fp32 accum. CTA 128x256, BK=64, 16 warps (2x8),
// warp tile 64x32, 2-stage cp.async.
#define BK 64
#define LDH 72
#define MATA (128 * LDH * 2)          /* 18,432 B (A hi or lo) */
#define MATBB (256 * LDH * 2)         /* 36,864 B (B, 256 rows) */
#define STAGEB (2 * MATA + MATBB)     /* 73,728 B */
#define GEMM_SMEM (2 * STAGEB)        /* 147,456 B */

template<bool SPLIT>
__global__ void __launch_bounds__(512, 1) hgemm_kernel(
    const __half* __restrict__ Ahg, const __half* __restrict__ Alg,
    const __half* __restrict__ Bhg,
    const float* __restrict__ bias, float* __restrict__ C,
    __half* __restrict__ Oh, __half* __restrict__ Ol,
    int M, int N, int K, int loN)
{
    extern __shared__ char smc[];
    const uint32_t sb = cvta_smem(smc);
    const int tid = threadIdx.x, wid = tid >> 5, lid = tid & 31;
    const int m0 = blockIdx.y * 128, n0 = blockIdx.x * 256;
    const int wm = wid >> 3, wn = wid & 7;

    const __half* Ah0 = Ahg + (size_t)m0 * K;
    const __half* Al0 = Alg + (size_t)m0 * K;
    const __half* Bh0 = Bhg + (size_t)n0 * K;

    auto load_stage = [&](int st, int kc) {
        const uint32_t base = sb + st * STAGEB;
        // A hi: 1024 chunks (2/thread)
        #pragma unroll
        for (int i = 0; i < 2; i++) {
            const int c = i * 512 + tid;
            const int row = c >> 3, seg = c & 7;
            cp16(base + (uint32_t)(row * 144 + seg * 16),
                 Ah0 + (size_t)row * K + kc * BK + seg * 8);
        }
        // A lo: 1024 chunks
        #pragma unroll
        for (int i = 0; i < 2; i++) {
            const int c = i * 512 + tid;
            const int row = c >> 3, seg = c & 7;
            cp16(base + MATA + (uint32_t)(row * 144 + seg * 16),
                 Al0 + (size_t)row * K + kc * BK + seg * 8);
        }
        // B: 2048 chunks (4/thread)
        #pragma unroll
        for (int i = 0; i < 4; i++) {
            const int c = i * 512 + tid;
            const int row = c >> 3, seg = c & 7;
            cp16(base + 2 * MATA + (uint32_t)(row * 144 + seg * 16),
                 Bh0 + (size_t)row * K + kc * BK + seg * 8);
        }
    };

    const int NC = K / BK;                  /* 32 */
    load_stage(0, 0); cp_commit();
    load_stage(1, 1); cp_commit();

    float acc[4][4][4];
    #pragma unroll
    for (int i = 0; i < 4; i++)
        #pragma unroll
        for (int j = 0; j < 4; j++)
            #pragma unroll
            for (int q = 0; q < 4; q++) acc[i][j][q] = 0.f;

    const int aRow = lid & 15, aColX = (lid & 16) ? 8 : 0;
    const int bRow = (lid & 7) + ((lid & 16) ? 8 : 0), bColX = (lid & 8) ? 8 : 0;

    for (int c = 0; c < NC; c++) {
        const int s = c & 1;
        cp_wait<1>();
        __syncthreads();
        const uint32_t stA = sb + s * STAGEB;
        const uint32_t stB = stA + 2 * MATA;

        #pragma unroll
        for (int ks = 0; ks < 4; ks++) {
            uint32_t bh[4][2];
            #pragma unroll
            for (int p = 0; p < 2; p++) {
                const uint32_t rb = stB +
                    (uint32_t)(((wn * 32 + p * 16 + bRow) * LDH + ks * 16 + bColX) * 2);
                uint32_t t0[4];
                ldsm4(t0, rb);
                bh[2*p][0]=t0[0]; bh[2*p][1]=t0[1]; bh[2*p+1][0]=t0[2]; bh[2*p+1][1]=t0[3];
            }
            #pragma unroll
            for (int mi = 0; mi < 4; mi++) {
                uint32_t ah[4], al[4];
                const uint32_t ra = stA +
                    (uint32_t)(((wm * 64 + mi * 16 + aRow) * LDH + ks * 16 + aColX) * 2);
                ldsm4(ah, ra);
                ldsm4(al, ra + MATA);
                #pragma unroll
                for (int nj = 0; nj < 4; nj++) {
                    mma16816(acc[mi][nj], ah, bh[nj]);
                    mma16816(acc[mi][nj], al, bh[nj]);
                }
            }
        }
        __syncthreads();
        if (c + 2 < NC) load_stage(s, c + 2);
        cp_commit();
    }

    const bool wantLo = SPLIT && (n0 < loN);
    #pragma unroll
    for (int mi = 0; mi < 4; mi++) {
        const int r0 = m0 + wm * 64 + mi * 16 + (lid >> 2);
        #pragma unroll
        for (int nj = 0; nj < 4; nj++) {
            const int col = n0 + wn * 32 + nj * 8 + (lid & 3) * 2;
            const float b0 = bias[col], b1 = bias[col + 1];
            const float v00 = acc[mi][nj][0] + b0, v01 = acc[mi][nj][1] + b1;
            const float v10 = acc[mi][nj][2] + b0, v11 = acc[mi][nj][3] + b1;
            if (SPLIT) {
                __half h0,l0,h1,l1;
                hsplit(v00,h0,l0); hsplit(v01,h1,l1);
                *(__half2*)&Oh[(size_t)r0 * N + col] = __halves2half2(h0, h1);
                if (wantLo) *(__half2*)&Ol[(size_t)r0 * N + col] = __halves2half2(l0, l1);
                hsplit(v10,h0,l0); hsplit(v11,h1,l1);
                *(__half2*)&Oh[(size_t)(r0+8) * N + col] = __halves2half2(h0, h1);
                if (wantLo) *(__half2*)&Ol[(size_t)(r0+8) * N + col] = __halves2half2(l0, l1);
            } else {
                *(float2*)(C + (size_t)r0 * N + col) = make_float2(v00, v01);
                *(float2*)(C + (size_t)(r0 + 8) * N + col) = make_float2(v10, v11);
            }
        }
    }
}

// ---------------- Flash attention on HMMA (causal, 2-term split) -----------
// CTA: 64 q rows x one (b,h); 4 warps x m16; 128 threads; K-tile 64,
// 2-stage KV (hi only) -> 104,448 B smem -> 2 CTAs/SM.
// NOTE: head dim = 128 halves = 16 segs of 8 -> 1024 chunks per 64-row tile.
#define FLD 136                       /* smem row stride in halves (272 B) */
#define FQL (64*FLD)                  /* Ql offset (halves) */
#define FST0 (2*64*FLD)               /* KV stage 0 offset (halves) */
#define FVH (64*FLD)                  /* V offset within stage */
#define FSTAGE (2*64*FLD)             /* Kh + Vh */
#define FLASH_SMEM ((FST0 + 2*FSTAGE)*2)   /* 104,448 B */

__global__ void __launch_bounds__(128, 2) flash_kernel(
    const __half* __restrict__ qh, const __half* __restrict__ ql)
{
    extern __shared__ char fsmc[];
    const uint32_t sb = cvta_smem(fsmc);
    const int tid = threadIdx.x, wid = tid >> 5, lid = tid & 31;
    const int b = blockIdx.z, h = blockIdx.y;
    const int qt = gridDim.x - 1 - blockIdx.x;    /* big tiles first */
    const int m0w = wid * 16;
    const size_t rowQ0 = (size_t)b * Sq + qt * 64;
    const int cQ = h * HDim, cK = Dm + h * HDim, cV = 2 * Dm + h * HDim;

    // Q tiles (hi+lo): 64 rows x 16 segs = 1024 chunks, 8 iters x 128 thr
    #pragma unroll
    for (int i = 0; i < 8; i++) {
        const int c = i * 128 + tid;
        const int r = c >> 4, seg = c & 15;
        const uint32_t so = (uint32_t)(r * FLD + seg * 8) * 2;
        const size_t g = (rowQ0 + r) * QKVN + cQ + seg * 8;
        cp16(sb + so, qh + g);
        cp16(sb + FQL*2 + so, ql + g);
    }

    auto load_kv = [&](int st, int kt) {
        const size_t rowK0 = (size_t)b * Sq + kt * 64;
        const uint32_t base = sb + (uint32_t)(FST0 + st * FSTAGE) * 2;
        #pragma unroll
        for (int i = 0; i < 8; i++) {
            const int c = i * 128 + tid;
            const int r = c >> 4, seg = c & 15;
            const uint32_t so = (uint32_t)(r * FLD + seg * 8) * 2;
            cp16(base + so,         qh + (rowK0 + r) * QKVN + cK + seg * 8);
            cp16(base + FVH*2 + so, qh + (rowK0 + r) * QKVN + cV + seg * 8);
        }
    };

    const int NT = qt + 1;
    load_kv(0, 0); cp_commit();
    if (1 < NT) load_kv(1, 1);
    cp_commit();

    float o[16][4];
    #pragma unroll
    for (int i = 0; i < 16; i++)
        #pragma unroll
        for (int j = 0; j < 4; j++) o[i][j] = 0.f;
    float mA = -1e30f, mB = -1e30f, lA = 0.f, lB = 0.f;

    const int aRow = lid & 15, aColX = (lid & 16) ? 8 : 0;
    const int bRow = (lid & 7) + ((lid & 16) ? 8 : 0), bColX = (lid & 8) ? 8 : 0;
    const int rA = lid >> 2;
    const int qgA = qt * 64 + m0w + rA, qgB = qgA + 8;
    const float scale = 0.08838834764831845f;   // 1/sqrt(128)

    for (int kt = 0; kt < NT; ++kt) {
        cp_wait<1>();
        __syncthreads();
        const uint32_t stb = sb + (uint32_t)(FST0 + (kt & 1) * FSTAGE) * 2;
        // ---- scores = Q K^T (2-term: (Qh+Ql)·Kh) ----
        float sc[8][4];
        #pragma unroll
        for (int i = 0; i < 8; i++)
            #pragma unroll
            for (int j = 0; j < 4; j++) sc[i][j] = 0.f;
        #pragma unroll
        for (int ks = 0; ks < 8; ks++) {
            uint32_t ah[4], al[4];
            const uint32_t qa = sb +
                (uint32_t)(((m0w + aRow) * FLD + ks * 16 + aColX) * 2);
            ldsm4(ah, qa);
            ldsm4(al, qa + FQL*2);
            #pragma unroll
            for (int np = 0; np < 4; np++) {
                uint32_t kh4[4];
                const uint32_t ka = stb +
                    (uint32_t)(((np * 16 + bRow) * FLD + ks * 16 + bColX) * 2);
                ldsm4(kh4, ka);
                uint32_t bh0[2] = {kh4[0], kh4[1]}, bh1[2] = {kh4[2], kh4[3]};
                mma16816(sc[2*np],   ah, bh0); mma16816(sc[2*np],   al, bh0);
                mma16816(sc[2*np+1], ah, bh1); mma16816(sc[2*np+1], al, bh1);
            }
        }
        // ---- scale + causal mask (diagonal tile only) ----
        #pragma unroll
        for (int nt = 0; nt < 8; nt++)
            #pragma unroll
            for (int j = 0; j < 4; j++) sc[nt][j] *= scale;
        if (kt == qt) {
            #pragma unroll
            for (int nt = 0; nt < 8; nt++) {
                const int kg = kt * 64 + nt * 8 + 2 * (lid & 3);
                if (kg     > qgA) sc[nt][0] = -1e30f;
                if (kg + 1 > qgA) sc[nt][1] = -1e30f;
                if (kg     > qgB) sc[nt][2] = -1e30f;
                if (kg + 1 > qgB) sc[nt][3] = -1e30f;
            }
        }
        // ---- online softmax ----
        float rmA = -1e30f, rmB = -1e30f;
        #pragma unroll
        for (int nt = 0; nt < 8; nt++) {
            rmA = fmaxf(rmA, fmaxf(sc[nt][0], sc[nt][1]));
            rmB = fmaxf(rmB, fmaxf(sc[nt][2], sc[nt][3]));
        }
        rmA = fmaxf(rmA, __shfl_xor_sync(0xffffffffu, rmA, 1));
        rmA = fmaxf(rmA, __shfl_xor_sync(0xffffffffu, rmA, 2));
        rmB = fmaxf(rmB, __shfl_xor_sync(0xffffffffu, rmB, 1));
        rmB = fmaxf(rmB, __shfl_xor_sync(0xffffffffu, rmB, 2));
        const float nmA = fmaxf(mA, rmA), nmB = fmaxf(mB, rmB);
        const float corrA = __expf(mA - nmA), corrB = __expf(mB - nmB);
        mA = nmA; mB = nmB;
        float rsA = 0.f, rsB = 0.f;
        #pragma unroll
        for (int nt = 0; nt < 8; nt++) {
            sc[nt][0] = __expf(sc[nt][0] - nmA); rsA += sc[nt][0];
            sc[nt][1] = __expf(sc[nt][1] - nmA); rsA += sc[nt][1];
            sc[nt][2] = __expf(sc[nt][2] - nmB); rsB += sc[nt][2];
            sc[nt][3] = __expf(sc[nt][3] - nmB); rsB += sc[nt][3];
        }
        rsA += __shfl_xor_sync(0xffffffffu, rsA, 1);
        rsA += __shfl_xor_sync(0xffffffffu, rsA, 2);
        rsB += __shfl_xor_sync(0xffffffffu, rsB, 1);
        rsB += __shfl_xor_sync(0xffffffffu, rsB, 2);
        lA = lA * corrA + rsA;
        lB = lB * corrB + rsB;
        #pragma unroll
        for (int d = 0; d < 16; d++) {
            o[d][0] *= corrA; o[d][1] *= corrA;
            o[d][2] *= corrB; o[d][3] *= corrB;
        }
        // ---- O += P V (2-term: (Ph+Pl)·Vh) ----
        #pragma unroll
        for (int k2 = 0; k2 < 4; k2++) {
            const float* t0 = sc[2*k2];
            const float* t1 = sc[2*k2+1];
            __half p00 = __float2half_rn(t0[0]), p01 = __float2half_rn(t0[1]);
            __half p02 = __float2half_rn(t0[2]), p03 = __float2half_rn(t0[3]);
            __half p10 = __float2half_rn(t1[0]), p11 = __float2half_rn(t1[1]);
            __half p12 = __float2half_rn(t1[2]), p13 = __float2half_rn(t1[3]);
            uint32_t aPh[4], aPl[4];
            aPh[0] = packh2(p00, p01); aPh[1] = packh2(p02, p03);
            aPh[2] = packh2(p10, p11); aPh[3] = packh2(p12, p13);
            aPl[0] = packh2(__float2half_rn(t0[0]-__half2float(p00)),
                            __float2half_rn(t0[1]-__half2float(p01)));
            aPl[1] = packh2(__float2half_rn(t0[2]-__half2float(p02)),
                            __float2half_rn(t0[3]-__half2float(p03)));
            aPl[2] = packh2(__float2half_rn(t1[0]-__half2float(p10)),
                            __float2half_rn(t1[1]-__half2float(p11)));
            aPl[3] = packh2(__float2half_rn(t1[2]-__half2float(p12)),
                            __float2half_rn(t1[3]-__half2float(p13)));
            #pragma unroll
            for (int dp = 0; dp < 8; dp++) {
                uint32_t vh4[4];
                const uint32_t va = stb + FVH*2 +
                    (uint32_t)(((k2 * 16 + aRow) * FLD + dp * 16 + aColX) * 2);
                ldsm4t(vh4, va);
                uint32_t b0[2] = {vh4[0], vh4[1]}, b1[2] = {vh4[2], vh4[3]};
                mma16816(o[2*dp],   aPh, b0); mma16816(o[2*dp],   aPl, b0);
                mma16816(o[2*dp+1], aPh, b1); mma16816(o[2*dp+1], aPl, b1);
            }
        }
        __syncthreads();
        if (kt + 2 < NT) load_kv(kt & 1, kt + 2);
        cp_commit();
    }

    // ---- epilogue: normalize, split to fp16 hi/lo for proj GEMM ----
    const float invA = 1.f / lA, invB = 1.f / lB;
    const size_t gA = (rowQ0 + m0w + rA) * Dm + h * HDim;
    const size_t gB = gA + (size_t)8 * Dm;
    #pragma unroll
    for (int nt = 0; nt < 16; nt++) {
        const int col = nt * 8 + 2 * (lid & 3);
        float x0 = o[nt][0] * invA, x1 = o[nt][1] * invA;
        __half h0,l0,h1,l1;
        hsplit(x0,h0,l0); hsplit(x1,h1,l1);
        *(__half2*)&g_ah[gA + col] = __halves2half2(h0, h1);
        *(__half2*)&g_al[gA + col] = __halves2half2(l0, l1);
        float x2 = o[nt][2] * invB, x3 = o[nt][3] * invB;
        hsplit(x2,h0,l0); hsplit(x3,h1,l1);
        *(__half2*)&g_ah[gB + col] = __halves2half2(h0, h1);
        *(__half2*)&g_al[gB + col] = __halves2half2(l0, l1);
    }
}

// ---------------- launch ----------------------------------------------------
extern "C" void kernel_launch(void* const* d_in, const int* in_sizes, int n_in,
                              void* d_out, int out_size)
{
    const float* hs    = (const float*)d_in[0];
    const float* gamma = (const float*)d_in[1];
    const float* beta  = (const float*)d_in[2];
    const float* Wqkv  = (const float*)d_in[3];
    const float* bqkv  = (const float*)d_in[4];
    const float* Wproj = (const float*)d_in[5];
    const float* bproj = (const float*)d_in[6];
    float* out = (float*)d_out;

    void *pxh,*pxl,*pqh,*pql,*pah,*pal,*pwqh,*pwph;
    cudaGetSymbolAddress(&pxh, g_xh);  cudaGetSymbolAddress(&pxl, g_xl);
    cudaGetSymbolAddress(&pqh, g_qh);  cudaGetSymbolAddress(&pql, g_ql);
    cudaGetSymbolAddress(&pah, g_ah);  cudaGetSymbolAddress(&pal, g_al);
    cudaGetSymbolAddress(&pwqh, g_wqh);
    cudaGetSymbolAddress(&pwph, g_wph);

    // LN -> fp16 hi/lo
    ln_kernel<<<Mrows, 256>>>(hs, gamma, beta);

    // weight transpose + fp16 (hi only)
    wconv_kernel<<<dim3(QKVN / 32, Dm / 32), dim3(32, 8)>>>(
        Wqkv, (__half*)pwqh, Dm, QKVN);
    wconv_kernel<<<dim3(Dm / 32, Dm / 32), dim3(32, 8)>>>(
        Wproj, (__half*)pwph, Dm, Dm);

    cudaFuncSetAttribute(hgemm_kernel<true>,
                         cudaFuncAttributeMaxDynamicSharedMemorySize, GEMM_SMEM);
    cudaFuncSetAttribute(hgemm_kernel<false>,
                         cudaFuncAttributeMaxDynamicSharedMemorySize, GEMM_SMEM);

    // QKV = x @ W_qkv + b  -> fp16 hi (+ lo for Q columns only)
    hgemm_kernel<true><<<dim3(QKVN / 256, Mrows / 128), 512, GEMM_SMEM>>>(
        (const __half*)pxh, (const __half*)pxl, (const __half*)pwqh,
        bqkv, nullptr, (__half*)pqh, (__half*)pql, Mrows, QKVN, Dm, Dm);

    // attention (HMMA flash, 64-row CTAs, 2 CTAs/SM)
    cudaFuncSetAttribute(flash_kernel,
                         cudaFuncAttributeMaxDynamicSharedMemorySize, FLASH_SMEM);
    flash_kernel<<<dim3(Sq / 64, Hh, Bsz), 128, FLASH_SMEM>>>(
        (const __half*)pqh, (const __half*)pql);

    // out = attn @ W_proj + b  -> f32
    hgemm_kernel<false><<<dim3(Dm / 256, Mrows / 128), 512, GEMM_SMEM>>>(
        (const __half*)pah, (const __half*)pal, (const __half*)pwph,
        bproj, out, nullptr, nullptr, Mrows, Dm, Dm, 0);
}

// round 17
// speedup vs baseline: 1.0717x; 1.0717x over previous
#include <cuda_runtime.h>
#include <cuda_fp16.h>
#include <math.h>
#include <stdint.h>

#define Bsz   4
#define Sq    2048
#define Dm    2048
#define Hh    16
#define HDim  128
#define Mrows (Bsz*Sq)      /* 8192 */
#define QKVN  (3*Dm)        /* 6144 */

// ---------------- scratch (device globals; no allocation allowed) ----------
__device__ __half g_xh[(size_t)Mrows * Dm];     // LN out hi/lo (fp16 split)
__device__ __half g_xl[(size_t)Mrows * Dm];
__device__ __half g_qh[(size_t)Mrows * QKVN];   // qkv projection hi/lo
__device__ __half g_ql[(size_t)Mrows * QKVN];   // (lo only consumed for Q cols)
__device__ __half g_ah[(size_t)Mrows * Dm];     // attn out hi/lo
__device__ __half g_al[(size_t)Mrows * Dm];
__device__ __half g_wqh[(size_t)QKVN * Dm];     // W_qkv^T hi
__device__ __half g_wph[(size_t)Dm * Dm];       // W_proj^T hi

// ---------------- small helpers --------------------------------------------
__device__ __forceinline__ void hsplit(float x, __half& h, __half& l) {
    h = __float2half_rn(x);
    l = __float2half_rn(x - __half2float(h));
}
__device__ __forceinline__ uint32_t packh2(__half a, __half b) {
    __half2 h = __halves2half2(a, b);
    return *(uint32_t*)&h;
}

// ---------------- Ampere-era primitives (valid on plain sm_103 target) -----
__device__ __forceinline__ uint32_t cvta_smem(const void* p) {
    return (uint32_t)__cvta_generic_to_shared(p);
}
__device__ __forceinline__ void cp16(uint32_t s, const void* g) {
    asm volatile("cp.async.cg.shared.global [%0], [%1], 16;" :: "r"(s), "l"(g));
}
__device__ __forceinline__ void cp_commit() {
    asm volatile("cp.async.commit_group;" ::: "memory");
}
template<int W> __device__ __forceinline__ void cp_wait() {
    asm volatile("cp.async.wait_group %0;" :: "n"(W) : "memory");
}
__device__ __forceinline__ void ldsm4(uint32_t* r, uint32_t addr) {
    asm volatile("ldmatrix.sync.aligned.m8n8.x4.shared.b16 {%0,%1,%2,%3}, [%4];"
                 : "=r"(r[0]), "=r"(r[1]), "=r"(r[2]), "=r"(r[3]) : "r"(addr));
}
__device__ __forceinline__ void ldsm4t(uint32_t* r, uint32_t addr) {
    asm volatile("ldmatrix.sync.aligned.m8n8.x4.trans.shared.b16 {%0,%1,%2,%3}, [%4];"
                 : "=r"(r[0]), "=r"(r[1]), "=r"(r[2]), "=r"(r[3]) : "r"(addr));
}
__device__ __forceinline__ void mma16816(float* c, const uint32_t* a, const uint32_t* b) {
    asm volatile("mma.sync.aligned.m16n8k16.row.col.f32.f16.f16.f32 "
                 "{%0,%1,%2,%3}, {%4,%5,%6,%7}, {%8,%9}, {%0,%1,%2,%3};"
                 : "+f"(c[0]), "+f"(c[1]), "+f"(c[2]), "+f"(c[3])
                 : "r"(a[0]), "r"(a[1]), "r"(a[2]), "r"(a[3]),
                   "r"(b[0]), "r"(b[1]));
}

// ---------------- LayerNorm: one block per row, writes fp16 hi/lo ----------
__global__ void __launch_bounds__(256) ln_kernel(
    const float* __restrict__ x, const float* __restrict__ gamma,
    const float* __restrict__ beta)
{
    const int row = blockIdx.x, t = threadIdx.x;
    const float4* xr = (const float4*)(x + (size_t)row * Dm);
    float4 v0 = xr[t], v1 = xr[t + 256];
    float s  = v0.x + v0.y + v0.z + v0.w + v1.x + v1.y + v1.z + v1.w;
    float ss = v0.x*v0.x + v0.y*v0.y + v0.z*v0.z + v0.w*v0.w
             + v1.x*v1.x + v1.y*v1.y + v1.z*v1.z + v1.w*v1.w;
    #pragma unroll
    for (int o = 16; o; o >>= 1) {
        s  += __shfl_xor_sync(0xffffffffu, s,  o);
        ss += __shfl_xor_sync(0xffffffffu, ss, o);
    }
    __shared__ float sh[16];
    const int w = t >> 5;
    if ((t & 31) == 0) { sh[w] = s; sh[8 + w] = ss; }
    __syncthreads();
    s = 0.f; ss = 0.f;
    #pragma unroll
    for (int i = 0; i < 8; i++) { s += sh[i]; ss += sh[8 + i]; }
    const float mean = s * (1.0f / Dm);
    const float var  = ss * (1.0f / Dm) - mean * mean;
    const float rstd = rsqrtf(var + 1e-5f);

    const float4* g4 = (const float4*)gamma;
    const float4* b4 = (const float4*)beta;
    float4 G0 = g4[t], G1 = g4[t + 256], B0 = b4[t], B1 = b4[t + 256];
    float4 o0, o1;
    o0.x = (v0.x - mean) * rstd * G0.x + B0.x;
    o0.y = (v0.y - mean) * rstd * G0.y + B0.y;
    o0.z = (v0.z - mean) * rstd * G0.z + B0.z;
    o0.w = (v0.w - mean) * rstd * G0.w + B0.w;
    o1.x = (v1.x - mean) * rstd * G1.x + B1.x;
    o1.y = (v1.y - mean) * rstd * G1.y + B1.y;
    o1.z = (v1.z - mean) * rstd * G1.z + B1.z;
    o1.w = (v1.w - mean) * rstd * G1.w + B1.w;

    auto store4 = [&](float4 v, int c0) {
        __half h0,l0,h1,l1,h2,l2,h3,l3;
        hsplit(v.x,h0,l0); hsplit(v.y,h1,l1); hsplit(v.z,h2,l2); hsplit(v.w,h3,l3);
        size_t base = (size_t)row * Dm + c0;
        *(__half2*)&g_xh[base]     = __halves2half2(h0, h1);
        *(__half2*)&g_xh[base + 2] = __halves2half2(h2, h3);
        *(__half2*)&g_xl[base]     = __halves2half2(l0, l1);
        *(__half2*)&g_xl[base + 2] = __halves2half2(l2, l3);
    };
    store4(o0, t * 4);
    store4(o1, 1024 + t * 4);
}

// ---------------- W transpose + fp16 convert (hi only) ---------------------
__global__ void wconv_kernel(const float* __restrict__ W,
                             __half* __restrict__ Th, int K, int N)
{
    __shared__ float tile[32][33];
    const int tx = threadIdx.x, ty = threadIdx.y;
    const int n0 = blockIdx.x * 32, k0 = blockIdx.y * 32;
    #pragma unroll
    for (int r = 0; r < 32; r += 8)
        tile[ty + r][tx] = W[(size_t)(k0 + ty + r) * N + n0 + tx];
    __syncthreads();
    #pragma unroll
    for (int r = 0; r < 32; r += 8) {
        Th[(size_t)(n0 + ty + r) * K + k0 + tx] = __float2half_rn(tile[tx][ty + r]);
    }
}

// ---------------- HMMA GEMM (R12 champion, unchanged) ----------------------
// 2-term fp16 split, fp32 accum. CTA 128x128, BK=64, 8 warps (2x4),
// 2-stage cp.async, 2 CTAs/SM.
#define BK 64
#define LDH 72
#define MATB (128 * LDH * 2)          /* 18,432 B per matrix */
#define STAGEB (3 * MATB)             /* Ah, Al, Bh = 55,296 B */
#define GEMM_SMEM (2 * STAGEB)        /* 110,592 B -> 2 CTAs/SM */

template<bool SPLIT>
__global__ void __launch_bounds__(256, 2) hgemm_kernel(
    const __half* __restrict__ Ahg, const __half* __restrict__ Alg,
    const __half* __restrict__ Bhg,
    const float* __restrict__ bias, float* __restrict__ C,
    __half* __restrict__ Oh, __half* __restrict__ Ol,
    int M, int N, int K, int loN)
{
    extern __shared__ char smc[];
    const uint32_t sb = cvta_smem(smc);
    const int tid = threadIdx.x, wid = tid >> 5, lid = tid & 31;
    const int m0 = blockIdx.y * 128, n0 = blockIdx.x * 128;
    const int wm = wid >> 2, wn = wid & 3;

    const __half* gp[3] = { Ahg + (size_t)m0 * K, Alg + (size_t)m0 * K,
                            Bhg + (size_t)n0 * K };

    auto load_stage = [&](int st, int kc) {
        const uint32_t base = sb + st * STAGEB;
        #pragma unroll
        for (int tI = 0; tI < 3; tI++) {
            const __half* g = gp[tI] + kc * BK;
            const uint32_t tb = base + tI * MATB;
            #pragma unroll
            for (int i = 0; i < 4; i++) {
                const int c = i * 256 + tid;
                const int row = c >> 3, seg = c & 7;
                cp16(tb + (uint32_t)(row * 144 + seg * 16),
                     g + (size_t)row * K + seg * 8);
            }
        }
    };

    const int NC = K / BK;                  /* 32 */
    load_stage(0, 0); cp_commit();
    load_stage(1, 1); cp_commit();

    float acc[4][4][4];
    #pragma unroll
    for (int i = 0; i < 4; i++)
        #pragma unroll
        for (int j = 0; j < 4; j++)
            #pragma unroll
            for (int q = 0; q < 4; q++) acc[i][j][q] = 0.f;

    const int aRow = lid & 15, aColX = (lid & 16) ? 8 : 0;
    const int bRow = (lid & 7) + ((lid & 16) ? 8 : 0), bColX = (lid & 8) ? 8 : 0;

    for (int c = 0; c < NC; c++) {
        const int s = c & 1;
        cp_wait<1>();
        __syncthreads();
        const uint32_t stA = sb + s * STAGEB;
        const uint32_t stB = stA + 2 * MATB;

        #pragma unroll
        for (int ks = 0; ks < 4; ks++) {
            uint32_t bh[4][2];
            #pragma unroll
            for (int p = 0; p < 2; p++) {
                const uint32_t rb = stB +
                    (uint32_t)(((wn * 32 + p * 16 + bRow) * LDH + ks * 16 + bColX) * 2);
                uint32_t t0[4];
                ldsm4(t0, rb);
                bh[2*p][0]=t0[0]; bh[2*p][1]=t0[1]; bh[2*p+1][0]=t0[2]; bh[2*p+1][1]=t0[3];
            }
            #pragma unroll
            for (int mi = 0; mi < 4; mi++) {
                uint32_t ah[4], al[4];
                const uint32_t ra = stA +
                    (uint32_t)(((wm * 64 + mi * 16 + aRow) * LDH + ks * 16 + aColX) * 2);
                ldsm4(ah, ra);
                ldsm4(al, ra + MATB);
                #pragma unroll
                for (int nj = 0; nj < 4; nj++) {
                    mma16816(acc[mi][nj], ah, bh[nj]);
                    mma16816(acc[mi][nj], al, bh[nj]);
                }
            }
        }
        __syncthreads();
        if (c + 2 < NC) load_stage(s, c + 2);
        cp_commit();
    }

    const bool wantLo = SPLIT && (n0 < loN);
    #pragma unroll
    for (int mi = 0; mi < 4; mi++) {
        const int r0 = m0 + wm * 64 + mi * 16 + (lid >> 2);
        #pragma unroll
        for (int nj = 0; nj < 4; nj++) {
            const int col = n0 + wn * 32 + nj * 8 + (lid & 3) * 2;
            const float b0 = bias[col], b1 = bias[col + 1];
            const float v00 = acc[mi][nj][0] + b0, v01 = acc[mi][nj][1] + b1;
            const float v10 = acc[mi][nj][2] + b0, v11 = acc[mi][nj][3] + b1;
            if (SPLIT) {
                __half h0,l0,h1,l1;
                hsplit(v00,h0,l0); hsplit(v01,h1,l1);
                *(__half2*)&Oh[(size_t)r0 * N + col] = __halves2half2(h0, h1);
                if (wantLo) *(__half2*)&Ol[(size_t)r0 * N + col] = __halves2half2(l0, l1);
                hsplit(v10,h0,l0); hsplit(v11,h1,l1);
                *(__half2*)&Oh[(size_t)(r0+8) * N + col] = __halves2half2(h0, h1);
                if (wantLo) *(__half2*)&Ol[(size_t)(r0+8) * N + col] = __halves2half2(l0, l1);
            } else {
                *(float2*)(C + (size_t)r0 * N + col) = make_float2(v00, v01);
                *(float2*)(C + (size_t)(r0 + 8) * N + col) = make_float2(v10, v11);
            }
        }
    }
}

// ---------------- Flash attention: Q in registers, 2 CTAs/SM ---------------
// CTA: 64 q rows x one (b,h); 4 warps x m16; 128 threads.
// Q hi/lo fragments loaded from global into registers (no Q smem).
// KV: 3 stages x (Kh+Vh), prefetch distance 2 -> ONE sync per k-tile.
#define FLD 136                       /* smem row stride in halves (272 B) */
#define FVH (64*FLD)                  /* V offset within stage (halves) */
#define FSTAGE (2*64*FLD)             /* Kh + Vh = 17,408 halves */
#define FLASH_SMEM (3*FSTAGE*2)       /* 104,448 B -> 2 CTAs/SM */

__global__ void __launch_bounds__(128, 2) flash_kernel(
    const __half* __restrict__ qh, const __half* __restrict__ ql)
{
    extern __shared__ char fsmc[];
    const uint32_t sb = cvta_smem(fsmc);
    const int tid = threadIdx.x, wid = tid >> 5, lid = tid & 31;
    const int b = blockIdx.z, h = blockIdx.y;
    const int qt = gridDim.x - 1 - blockIdx.x;    /* big tiles first */
    const int m0w = wid * 16;
    const size_t rowQ0 = (size_t)b * Sq + qt * 64;
    const int cQ = h * HDim, cK = Dm + h * HDim, cV = 2 * Dm + h * HDim;

    auto load_kv = [&](int st, int kt) {
        const size_t rowK0 = (size_t)b * Sq + kt * 64;
        const uint32_t base = sb + (uint32_t)(st * FSTAGE) * 2;
        #pragma unroll
        for (int i = 0; i < 8; i++) {
            const int c = i * 128 + tid;
            const int r = c >> 4, seg = c & 15;
            const uint32_t so = (uint32_t)(r * FLD + seg * 8) * 2;
            cp16(base + so,         qh + (rowK0 + r) * QKVN + cK + seg * 8);
            cp16(base + FVH*2 + so, qh + (rowK0 + r) * QKVN + cV + seg * 8);
        }
    };

    const int NT = qt + 1;
    load_kv(0, 0); cp_commit();
    if (1 < NT) { load_kv(1, 1); } cp_commit();

    // ---- Q fragments (hi+lo) straight from global into registers ----
    // mma m16n8k16 A layout: rows {lid>>2, lid>>2+8}, cols {2(lid&3), +8}
    uint32_t qah[8][4], qal[8][4];
    {
        const int fr = lid >> 2, fc = 2 * (lid & 3);
        const size_t qr0 = (rowQ0 + m0w + fr) * QKVN + cQ;
        const size_t qr1 = (rowQ0 + m0w + fr + 8) * QKVN + cQ;
        #pragma unroll
        for (int ks = 0; ks < 8; ks++) {
            const int c0 = ks * 16 + fc, c1 = c0 + 8;
            qah[ks][0] = *(const uint32_t*)(qh + qr0 + c0);
            qah[ks][1] = *(const uint32_t*)(qh + qr1 + c0);
            qah[ks][2] = *(const uint32_t*)(qh + qr0 + c1);
            qah[ks][3] = *(const uint32_t*)(qh + qr1 + c1);
            qal[ks][0] = *(const uint32_t*)(ql + qr0 + c0);
            qal[ks][1] = *(const uint32_t*)(ql + qr1 + c0);
            qal[ks][2] = *(const uint32_t*)(ql + qr0 + c1);
            qal[ks][3] = *(const uint32_t*)(ql + qr1 + c1);
        }
    }

    float o[16][4];
    #pragma unroll
    for (int i = 0; i < 16; i++)
        #pragma unroll
        for (int j = 0; j < 4; j++) o[i][j] = 0.f;
    float mA = -1e30f, mB = -1e30f, lA = 0.f, lB = 0.f;

    const int aRow = lid & 15, aColX = (lid & 16) ? 8 : 0;
    const int bRow = (lid & 7) + ((lid & 16) ? 8 : 0), bColX = (lid & 8) ? 8 : 0;
    const int rA = lid >> 2;
    const int qgA = qt * 64 + m0w + rA, qgB = qgA + 8;
    const float scale = 0.08838834764831845f;   // 1/sqrt(128)

    for (int kt = 0; kt < NT; ++kt) {
        cp_wait<1>();
        __syncthreads();                        // orders prev reads before overwrite
        if (kt + 2 < NT) load_kv((kt + 2) % 3, kt + 2);
        cp_commit();
        const uint32_t stb = sb + (uint32_t)((kt % 3) * FSTAGE) * 2;

        // ---- scores = Q K^T (2-term: (Qh+Ql)·Kh) ----
        float sc[8][4];
        #pragma unroll
        for (int i = 0; i < 8; i++)
            #pragma unroll
            for (int j = 0; j < 4; j++) sc[i][j] = 0.f;
        #pragma unroll
        for (int ks = 0; ks < 8; ks++) {
            #pragma unroll
            for (int np = 0; np < 4; np++) {
                uint32_t kh4[4];
                const uint32_t ka = stb +
                    (uint32_t)(((np * 16 + bRow) * FLD + ks * 16 + bColX) * 2);
                ldsm4(kh4, ka);
                uint32_t bh0[2] = {kh4[0], kh4[1]}, bh1[2] = {kh4[2], kh4[3]};
                mma16816(sc[2*np],   qah[ks], bh0); mma16816(sc[2*np],   qal[ks], bh0);
                mma16816(sc[2*np+1], qah[ks], bh1); mma16816(sc[2*np+1], qal[ks], bh1);
            }
        }
        // ---- scale + causal mask (diagonal tile only) ----
        #pragma unroll
        for (int nt = 0; nt < 8; nt++)
            #pragma unroll
            for (int j = 0; j < 4; j++) sc[nt][j] *= scale;
        if (kt == qt) {
            #pragma unroll
            for (int nt = 0; nt < 8; nt++) {
                const int kg = kt * 64 + nt * 8 + 2 * (lid & 3);
                if (kg     > qgA) sc[nt][0] = -1e30f;
                if (kg + 1 > qgA) sc[nt][1] = -1e30f;
                if (kg     > qgB) sc[nt][2] = -1e30f;
                if (kg + 1 > qgB) sc[nt][3] = -1e30f;
            }
        }
        // ---- online softmax ----
        float rmA = -1e30f, rmB = -1e30f;
        #pragma unroll
        for (int nt = 0; nt < 8; nt++) {
            rmA = fmaxf(rmA, fmaxf(sc[nt][0], sc[nt][1]));
            rmB = fmaxf(rmB, fmaxf(sc[nt][2], sc[nt][3]));
        }
        rmA = fmaxf(rmA, __shfl_xor_sync(0xffffffffu, rmA, 1));
        rmA = fmaxf(rmA, __shfl_xor_sync(0xffffffffu, rmA, 2));
        rmB = fmaxf(rmB, __shfl_xor_sync(0xffffffffu, rmB, 1));
        rmB = fmaxf(rmB, __shfl_xor_sync(0xffffffffu, rmB, 2));
        const float nmA = fmaxf(mA, rmA), nmB = fmaxf(mB, rmB);
        const float corrA = __expf(mA - nmA), corrB = __expf(mB - nmB);
        mA = nmA; mB = nmB;
        float rsA = 0.f, rsB = 0.f;
        #pragma unroll
        for (int nt = 0; nt < 8; nt++) {
            sc[nt][0] = __expf(sc[nt][0] - nmA); rsA += sc[nt][0];
            sc[nt][1] = __expf(sc[nt][1] - nmA); rsA += sc[nt][1];
            sc[nt][2] = __expf(sc[nt][2] - nmB); rsB += sc[nt][2];
            sc[nt][3] = __expf(sc[nt][3] - nmB); rsB += sc[nt][3];
        }
        rsA += __shfl_xor_sync(0xffffffffu, rsA, 1);
        rsA += __shfl_xor_sync(0xffffffffu, rsA, 2);
        rsB += __shfl_xor_sync(0xffffffffu, rsB, 1);
        rsB += __shfl_xor_sync(0xffffffffu, rsB, 2);
        lA = lA * corrA + rsA;
        lB = lB * corrB + rsB;
        #pragma unroll
        for (int d = 0; d < 16; d++) {
            o[d][0] *= corrA; o[d][1] *= corrA;
            o[d][2] *= corrB; o[d][3] *= corrB;
        }
        // ---- O += P V (2-term: (Ph+Pl)·Vh) ----
        #pragma unroll
        for (int k2 = 0; k2 < 4; k2++) {
            const float* t0 = sc[2*k2];
            const float* t1 = sc[2*k2+1];
            __half p00 = __float2half_rn(t0[0]), p01 = __float2half_rn(t0[1]);
            __half p02 = __float2half_rn(t0[2]), p03 = __float2half_rn(t0[3]);
            __half p10 = __float2half_rn(t1[0]), p11 = __float2half_rn(t1[1]);
            __half p12 = __float2half_rn(t1[2]), p13 = __float2half_rn(t1[3]);
            uint32_t aPh[4], aPl[4];
            aPh[0] = packh2(p00, p01); aPh[1] = packh2(p02, p03);
            aPh[2] = packh2(p10, p11); aPh[3] = packh2(p12, p13);
            aPl[0] = packh2(__float2half_rn(t0[0]-__half2float(p00)),
                            __float2half_rn(t0[1]-__half2float(p01)));
            aPl[1] = packh2(__float2half_rn(t0[2]-__half2float(p02)),
                            __float2half_rn(t0[3]-__half2float(p03)));
            aPl[2] = packh2(__float2half_rn(t1[0]-__half2float(p10)),
                            __float2half_rn(t1[1]-__half2float(p11)));
            aPl[3] = packh2(__float2half_rn(t1[2]-__half2float(p12)),
                            __float2half_rn(t1[3]-__half2float(p13)));
            #pragma unroll
            for (int dp = 0; dp < 8; dp++) {
                uint32_t vh4[4];
                const uint32_t va = stb + FVH*2 +
                    (uint32_t)(((k2 * 16 + aRow) * FLD + dp * 16 + aColX) * 2);
                ldsm4t(vh4, va);
                uint32_t b0[2] = {vh4[0], vh4[1]}, b1[2] = {vh4[2], vh4[3]};
                mma16816(o[2*dp],   aPh, b0); mma16816(o[2*dp],   aPl, b0);
                mma16816(o[2*dp+1], aPh, b1); mma16816(o[2*dp+1], aPl, b1);
            }
        }
    }

    // ---- epilogue: normalize, split to fp16 hi/lo for proj GEMM ----
    const float invA = 1.f / lA, invB = 1.f / lB;
    const size_t gA = (rowQ0 + m0w + rA) * Dm + h * HDim;
    const size_t gB = gA + (size_t)8 * Dm;
    #pragma unroll
    for (int nt = 0; nt < 16; nt++) {
        const int col = nt * 8 + 2 * (lid & 3);
        float x0 = o[nt][0] * invA, x1 = o[nt][1] * invA;
        __half h0,l0,h1,l1;
        hsplit(x0,h0,l0); hsplit(x1,h1,l1);
        *(__half2*)&g_ah[gA + col] = __halves2half2(h0, h1);
        *(__half2*)&g_al[gA + col] = __halves2half2(l0, l1);
        float x2 = o[nt][2] * invB, x3 = o[nt][3] * invB;
        hsplit(x2,h0,l0); hsplit(x3,h1,l1);
        *(__half2*)&g_ah[gB + col] = __halves2half2(h0, h1);
        *(__half2*)&g_al[gB + col] = __halves2half2(l0, l1);
    }
}

// ---------------- launch ----------------------------------------------------
extern "C" void kernel_launch(void* const* d_in, const int* in_sizes, int n_in,
                              void* d_out, int out_size)
{
    const float* hs    = (const float*)d_in[0];
    const float* gamma = (const float*)d_in[1];
    const float* beta  = (const float*)d_in[2];
    const float* Wqkv  = (const float*)d_in[3];
    const float* bqkv  = (const float*)d_in[4];
    const float* Wproj = (const float*)d_in[5];
    const float* bproj = (const float*)d_in[6];
    float* out = (float*)d_out;

    void *pxh,*pxl,*pqh,*pql,*pah,*pal,*pwqh,*pwph;
    cudaGetSymbolAddress(&pxh, g_xh);  cudaGetSymbolAddress(&pxl, g_xl);
    cudaGetSymbolAddress(&pqh, g_qh);  cudaGetSymbolAddress(&pql, g_ql);
    cudaGetSymbolAddress(&pah, g_ah);  cudaGetSymbolAddress(&pal, g_al);
    cudaGetSymbolAddress(&pwqh, g_wqh);
    cudaGetSymbolAddress(&pwph, g_wph);

    // LN -> fp16 hi/lo
    ln_kernel<<<Mrows, 256>>>(hs, gamma, beta);

    // weight transpose + fp16 (hi only)
    wconv_kernel<<<dim3(QKVN / 32, Dm / 32), dim3(32, 8)>>>(
        Wqkv, (__half*)pwqh, Dm, QKVN);
    wconv_kernel<<<dim3(Dm / 32, Dm / 32), dim3(32, 8)>>>(
        Wproj, (__half*)pwph, Dm, Dm);

    cudaFuncSetAttribute(hgemm_kernel<true>,
                         cudaFuncAttributeMaxDynamicSharedMemorySize, GEMM_SMEM);
    cudaFuncSetAttribute(hgemm_kernel<false>,
                         cudaFuncAttributeMaxDynamicSharedMemorySize, GEMM_SMEM);

    // QKV = x @ W_qkv + b  -> fp16 hi (+ lo for Q columns only)
    hgemm_kernel<true><<<dim3(QKVN / 128, Mrows / 128), 256, GEMM_SMEM>>>(
        (const __half*)pxh, (const __half*)pxl, (const __half*)pwqh,
        bqkv, nullptr, (__half*)pqh, (__half*)pql, Mrows, QKVN, Dm, Dm);

    // attention (HMMA flash, Q-in-registers, 2 CTAs/SM)
    cudaFuncSetAttribute(flash_kernel,
                         cudaFuncAttributeMaxDynamicSharedMemorySize, FLASH_SMEM);
    flash_kernel<<<dim3(Sq / 64, Hh, Bsz), 128, FLASH_SMEM>>>(
        (const __half*)pqh, (const __half*)pql);

    // out = attn @ W_proj + b  -> f32
    hgemm_kernel<false><<<dim3(Dm / 128, Mrows / 128), 256, GEMM_SMEM>>>(
        (const __half*)pah, (const __half*)pal, (const __half*)pwph,
        bproj, out, nullptr, nullptr, Mrows, Dm, Dm, 0);
}